// round 15
// baseline (speedup 1.0000x reference)
#include <cuda_runtime.h>
#include <cuda_bf16.h>
#include <math.h>
#include <stdint.h>

#define BB    16
#define TT    10240
#define CC    256
#define KERN  10
#define STRD  5
#define LOUT  2047
#define KST   12
#define NNEG  10
#define EPSV  1e-5f
#define RV    32752          // B*LOUT valid rows
#define RP    32768          // padded rows (256 tiles x 128)
#define NTILE 256            // M-tiles of 128
#define NPART 128            // stats partials per channel (16 b x 8 ltiles)

// ---- GEMM smem: double-buffered 40KB stages (K-chunk 32, 64B rows, XOR swizzle)
#define OFF_A   0
#define OFF_BHI 8192
#define OFF_BLO 24576
#define STAGE   40960
#define OFF_RED (2 * STAGE)               // 81920: float red[4][128]
#define SMEM_DYN (OFF_RED + 2048)         // 83968 bytes

// ---------------- device scratch (no allocation allowed) ----------------
__device__ __align__(16) float         g_scale[CC];
__device__ __align__(16) float         g_shift[CC];
__device__ __align__(16) double        g_sp1[CC * NPART];
__device__ __align__(16) double        g_sp2[CC * NPART];
__device__ __align__(16) float         g_Q[(size_t)KST * BB * LOUT];
__device__ __align__(16) double        g_part[KST * BB];
__device__ __align__(16) float         g_Zf [(size_t)RP * CC];
__device__ __align__(16) __nv_bfloat16 g_Zhi[(size_t)RP * CC];
__device__ __align__(16) __nv_bfloat16 g_Zlo[(size_t)RP * CC];
__device__ __align__(16) __nv_bfloat16 g_Shi[(size_t)KST * CC * CC];  // [k][n][c] = S[c][n], S=(W+W^T)/2
__device__ __align__(16) __nv_bfloat16 g_Slo[(size_t)KST * CC * CC];

// ---------------- helpers (baseline sm_80+ PTX only) ----------------
__device__ __forceinline__ uint32_t smem_u32(const void* p) {
    uint32_t a;
    asm("{ .reg .u64 t; cvta.to.shared.u64 t, %1; cvt.u32.u64 %0, t; }" : "=r"(a) : "l"(p));
    return a;
}
__device__ __forceinline__ void cp16(uint32_t dst, const void* src) {
    asm volatile("cp.async.cg.shared.global [%0], [%1], 16;" :: "r"(dst), "l"(src));
}
#define CP_COMMIT() asm volatile("cp.async.commit_group;" ::: "memory")
#define CP_WAIT(n)  asm volatile("cp.async.wait_group %0;" :: "n"(n) : "memory")

#define LDSM4(r0, r1, r2, r3, addr) \
    asm volatile("ldmatrix.sync.aligned.m8n8.x4.shared.b16 {%0,%1,%2,%3}, [%4];" \
        : "=r"(r0), "=r"(r1), "=r"(r2), "=r"(r3) : "r"(addr))

__device__ __forceinline__ void mma16816(float* c, const uint32_t* a, const uint32_t* b) {
    asm volatile("mma.sync.aligned.m16n8k16.row.col.f32.bf16.bf16.f32 "
        "{%0,%1,%2,%3}, {%4,%5,%6,%7}, {%8,%9}, {%0,%1,%2,%3};"
        : "+f"(c[0]), "+f"(c[1]), "+f"(c[2]), "+f"(c[3])
        : "r"(a[0]), "r"(a[1]), "r"(a[2]), "r"(a[3]), "r"(b[0]), "r"(b[1]));
}

// ---------------- K1a: conv+relu partial stats, smem-staged x ----------------
__global__ __launch_bounds__(256) void k_stats_p(
    const float* __restrict__ x, const float* __restrict__ w,
    const float* __restrict__ bias)
{
    __shared__ float xs[256 * STRD + KERN];
    const int lt = blockIdx.x, b = blockIdx.y;
    const int l0 = lt * 256;
    const int cnt = (l0 + 256 <= LOUT) ? 256 : (LOUT - l0);
    const int base = l0 * STRD;
    for (int i = threadIdx.x; i < 256 * STRD + KERN; i += 256) {
        int g = base + i;
        xs[i] = (g < TT) ? x[(size_t)b * TT + g] : 0.0f;
    }
    __syncthreads();

    const int c = threadIdx.x;
    float wr[KERN];
#pragma unroll
    for (int i = 0; i < KERN; i++) wr[i] = __ldg(&w[c * KERN + i]);
    const float bc = __ldg(&bias[c]);
    double s1 = 0.0, s2 = 0.0;
    for (int l = 0; l < cnt; l++) {
        float h = bc;
#pragma unroll
        for (int i = 0; i < KERN; i++) h = fmaf(xs[l * STRD + i], wr[i], h);
        h = fmaxf(h, 0.0f);
        s1 += (double)h;
        s2 += (double)h * (double)h;
    }
    g_sp1[c * NPART + b * 8 + lt] = s1;
    g_sp2[c * NPART + b * 8 + lt] = s2;
}

// ---------------- K1b: finalize BN scale/shift + pad Z tail rows ----------------
__global__ __launch_bounds__(256) void k_stats_f(
    const float* __restrict__ gamma, const float* __restrict__ beta)
{
    int c = threadIdx.x;
    double s1 = 0.0, s2 = 0.0;
#pragma unroll 8
    for (int j = 0; j < NPART; j++) { s1 += g_sp1[c * NPART + j]; s2 += g_sp2[c * NPART + j]; }
    double N = (double)BB * LOUT;
    double mu = s1 / N;
    double var = s2 / N - mu * mu;
    double rs = 1.0 / sqrt(var + (double)EPSV);
    float sc = (float)((double)gamma[c] * rs);
    g_scale[c] = sc;
    g_shift[c] = beta[c] - (float)mu * sc;
    __nv_bfloat16 z0 = __float2bfloat16(0.0f);
#pragma unroll
    for (int r = 0; r < RP - RV; r++) {
        size_t o = (size_t)(RV + r) * CC + c;
        g_Zf[o]  = 0.0f;
        g_Zhi[o] = z0;
        g_Zlo[o] = z0;
    }
}

// ---------------- K2: fused conv+BN -> d_out + Z split  (+ S split, b>=16) ----
__global__ __launch_bounds__(256) void k_fuse_w(
    const float* __restrict__ x, const float* __restrict__ w,
    const float* __restrict__ bias, const float* __restrict__ trw,
    float* __restrict__ out)
{
    __shared__ float sh[168 + 256 * 33];
    const int tid = threadIdx.x;

    if (blockIdx.y < 16) {
        float* xs = sh;
        float* ht = sh + 168;                 // [256][33]
        const int l0 = blockIdx.x * 32;
        const int b  = blockIdx.y;

        const int base = l0 * STRD;
        for (int i = tid; i < 165; i += 256) {
            int g = base + i;
            xs[i] = (g < TT) ? x[(size_t)b * TT + g] : 0.0f;
        }
        __syncthreads();

        {   // thread = channel
            const int c = tid;
            float wr[KERN];
#pragma unroll
            for (int i = 0; i < KERN; i++) wr[i] = __ldg(&w[c * KERN + i]);
            const float bc = __ldg(&bias[c]);
            const float sc = g_scale[c], shi = g_shift[c];
#pragma unroll
            for (int l = 0; l < 32; l++) {
                float h = bc;
#pragma unroll
                for (int i = 0; i < KERN; i++) h = fmaf(xs[l * STRD + i], wr[i], h);
                h = fmaxf(h, 0.0f);
                ht[c * 33 + l] = fmaf(h, sc, shi);
            }
        }
        __syncthreads();

        {   // d_out[b,c,l] coalesced along l
            const int l = tid & 31;
            const int lg = l0 + l;
            if (lg < LOUT) {
#pragma unroll
                for (int j = 0; j < 32; j++) {
                    int c = (tid >> 5) + j * 8;
                    out[((size_t)b * CC + c) * LOUT + lg] = ht[c * 33 + l];
                }
            }
        }
        {   // Z arrays [r][c], c = tid coalesced
            const int c = tid;
#pragma unroll 4
            for (int l = 0; l < 32; l++) {
                int lg = l0 + l;
                if (lg >= LOUT) break;
                size_t r = (size_t)b * LOUT + lg;
                float v = ht[c * 33 + l];
                __nv_bfloat16 hi = __float2bfloat16(v);
                __nv_bfloat16 lo = __float2bfloat16(v - __bfloat162float(hi));
                g_Zf [r * CC + c] = v;
                g_Zhi[r * CC + c] = hi;
                g_Zlo[r * CC + c] = lo;
            }
        }
    } else {
        // S = (W + W^T)/2 transpose+split: 128 blocks x 6 tiles = 768 = 12k x 8 x 8
        float* t1 = sh;                       // [32][33]  W[c][n] tile
        float* t2 = sh + 32 * 33;             // [32][33]  W[n][c] tile
        const int idx = (blockIdx.y - 16) * 64 + blockIdx.x;
        for (int j = 0; j < 6; j++) {
            const int tno = idx * 6 + j;
            const int k = tno >> 6;
            const int rem = tno & 63;
            const int c0 = (rem >> 3) << 5, n0 = (rem & 7) << 5;
            const float* W = trw + (size_t)k * CC * CC;
            for (int i = tid; i < 32 * 32; i += 256) {
                int rr = i >> 5, cc2 = i & 31;
                t1[rr * 33 + cc2] = W[(size_t)(c0 + rr) * CC + n0 + cc2];
                t2[rr * 33 + cc2] = W[(size_t)(n0 + rr) * CC + c0 + cc2];
            }
            __syncthreads();
            for (int i = tid; i < 32 * 32; i += 256) {
                int nn = i >> 5, cc = i & 31;
                float v = 0.5f * (t1[cc * 33 + nn] + t2[nn * 33 + cc]);
                __nv_bfloat16 hi = __float2bfloat16(v);
                __nv_bfloat16 lo = __float2bfloat16(v - __bfloat162float(hi));
                size_t o = ((size_t)k * CC + n0 + nn) * CC + c0 + cc;
                g_Shi[o] = hi;
                g_Slo[o] = lo;
            }
            __syncthreads();
        }
    }
}

// ---------------- K3: HMMA 2-pass symmetric GEMM, double-buffered ----------------
// CTA = (k, m-tile 128). 8 warps 2Mx4N, warp tile 64x64.
// K-chunk 32 (64B rows, swizzle u^((row>>1)&3)); 2 stages of 40KB, cp.async pipelined.
// U = zhi^T S.  Q = U.(zf+zlo) + b.zf.
__global__ __launch_bounds__(256) void k_gemm(const float* __restrict__ trb)
{
    extern __shared__ char smem[];
    const uint32_t sb = smem_u32(smem);
    const int tid  = threadIdx.x;
    const int lane = tid & 31;
    const int w    = tid >> 5;
    const int mw   = w >> 2, nw = w & 3;
    const int k    = blockIdx.x;
    const int mt   = blockIdx.y;
    const int r0   = mt * 128;
    const int rbase = mw * 64, nbase = nw * 64;

    const __nv_bfloat16* Ah = g_Zhi + (size_t)r0 * CC;
    const __nv_bfloat16* Bh = g_Shi + (size_t)k * CC * CC;
    const __nv_bfloat16* Bl = g_Slo + (size_t)k * CC * CC;

    // chunk co (K offset = kc*32 bf16), stage st
    auto load_chunk = [&](int co, int st) {
        const uint32_t s0 = sb + st * STAGE;
#pragma unroll
        for (int t = 0; t < 2; t++) {         // A: 128 rows x 4 units = 512 ops
            int i = tid + t * 256;
            int row = i >> 2, u = i & 3;
            uint32_t d = (uint32_t)(row * 64 + ((u ^ ((row >> 1) & 3)) << 4));
            cp16(s0 + OFF_A + d, Ah + (size_t)row * CC + co + u * 8);
        }
#pragma unroll
        for (int t = 0; t < 4; t++) {         // B: 256 rows x 4 units = 1024 ops each
            int i = tid + t * 256;
            int row = i >> 2, u = i & 3;
            uint32_t d = (uint32_t)(row * 64 + ((u ^ ((row >> 1) & 3)) << 4));
            cp16(s0 + OFF_BHI + d, Bh + (size_t)row * CC + co + u * 8);
            cp16(s0 + OFF_BLO + d, Bl + (size_t)row * CC + co + u * 8);
        }
        CP_COMMIT();
    };

    float c[4][8][4];
#pragma unroll
    for (int mi = 0; mi < 4; mi++)
#pragma unroll
        for (int ni = 0; ni < 8; ni++)
#pragma unroll
            for (int j = 0; j < 4; j++) c[mi][ni][j] = 0.0f;

    // per-lane ldmatrix row bases; 64B rows, perm = (row>>1)&3
    const uint32_t aRow = (uint32_t)(rbase + (lane & 15));
    const uint32_t pmA  = (aRow >> 1) & 3;
    const uint32_t hiA  = (uint32_t)(lane >> 4);
    const uint32_t aBase = (uint32_t)(aRow * 64);
    const uint32_t bRow = (uint32_t)(nbase + (lane & 7) + ((lane >> 4) << 3));
    const uint32_t pmB  = (bRow >> 1) & 3;
    const uint32_t hiB  = (uint32_t)((lane >> 3) & 1);
    const uint32_t bBase = (uint32_t)(bRow * 64);

    load_chunk(0, 0);

    for (int kc = 0; kc < 8; kc++) {
        if (kc < 7) load_chunk((kc + 1) * 32, (kc + 1) & 1);
        if (kc < 7) { CP_WAIT(1); } else { CP_WAIT(0); }
        __syncthreads();

        const uint32_t s0 = sb + (kc & 1) * STAGE;
#pragma unroll
        for (int ks = 0; ks < 2; ks++) {
            const uint32_t colA = ((((uint32_t)(ks << 1) | hiA) ^ pmA) << 4);
            const uint32_t colB = ((((uint32_t)(ks << 1) | hiB) ^ pmB) << 4);
            const uint32_t pAH = s0 + OFF_A   + aBase + colA;
            const uint32_t pBH = s0 + OFF_BHI + bBase + colB;
            const uint32_t pBL = s0 + OFF_BLO + bBase + colB;

            uint32_t aH[4][4], bH[8][2];
#pragma unroll
            for (int mi = 0; mi < 4; mi++)
                LDSM4(aH[mi][0], aH[mi][1], aH[mi][2], aH[mi][3], pAH + mi * 1024);
#pragma unroll
            for (int p = 0; p < 4; p++)
                LDSM4(bH[2 * p][0], bH[2 * p][1], bH[2 * p + 1][0], bH[2 * p + 1][1],
                      pBH + p * 1024);
            // pass 0: zhi * Shi
#pragma unroll
            for (int mi = 0; mi < 4; mi++)
#pragma unroll
                for (int ni = 0; ni < 8; ni++) mma16816(c[mi][ni], aH[mi], bH[ni]);
            // pass 1: zhi * Slo
            {
                uint32_t bL[8][2];
#pragma unroll
                for (int p = 0; p < 4; p++)
                    LDSM4(bL[2 * p][0], bL[2 * p][1], bL[2 * p + 1][0], bL[2 * p + 1][1],
                          pBL + p * 1024);
#pragma unroll
                for (int mi = 0; mi < 4; mi++)
#pragma unroll
                    for (int ni = 0; ni < 8; ni++) mma16816(c[mi][ni], aH[mi], bL[ni]);
            }
        }
        __syncthreads();
    }

    // ---- epilogue: Q[r] = sum_n U[r,n]*(zf[r,n] + zlo[r,n]) + b_n*zf[r,n]
    float2 bias[8];
#pragma unroll
    for (int ni = 0; ni < 8; ni++)
        bias[ni] = __ldg((const float2*)&trb[k * CC + nbase + ni * 8 + (lane & 3) * 2]);

    float* red = (float*)(smem + OFF_RED);
    float qlo[4], qhi[4];
#pragma unroll
    for (int mi = 0; mi < 4; mi++) { qlo[mi] = 0.0f; qhi[mi] = 0.0f; }
#pragma unroll
    for (int mi = 0; mi < 4; mi++) {
        int rlo = r0 + rbase + mi * 16 + (lane >> 2);
#pragma unroll
        for (int ni = 0; ni < 8; ni++) {
            int col = nbase + ni * 8 + (lane & 3) * 2;
            float2 zl = *(const float2*)&g_Zf[(size_t)rlo * CC + col];
            float2 zh = *(const float2*)&g_Zf[(size_t)(rlo + 8) * CC + col];
            __nv_bfloat162 el = *(const __nv_bfloat162*)&g_Zlo[(size_t)rlo * CC + col];
            __nv_bfloat162 eh = *(const __nv_bfloat162*)&g_Zlo[(size_t)(rlo + 8) * CC + col];
            qlo[mi] = fmaf(c[mi][ni][0], zl.x + __low2float(el), qlo[mi]);
            qlo[mi] = fmaf(c[mi][ni][1], zl.y + __high2float(el), qlo[mi]);
            qhi[mi] = fmaf(c[mi][ni][2], zh.x + __low2float(eh), qhi[mi]);
            qhi[mi] = fmaf(c[mi][ni][3], zh.y + __high2float(eh), qhi[mi]);
            qlo[mi] = fmaf(bias[ni].x, zl.x, qlo[mi]);
            qlo[mi] = fmaf(bias[ni].y, zl.y, qlo[mi]);
            qhi[mi] = fmaf(bias[ni].x, zh.x, qhi[mi]);
            qhi[mi] = fmaf(bias[ni].y, zh.y, qhi[mi]);
        }
    }
#pragma unroll
    for (int m = 1; m <= 2; m <<= 1) {
#pragma unroll
        for (int mi = 0; mi < 4; mi++) {
            qlo[mi] += __shfl_xor_sync(0xffffffffu, qlo[mi], m);
            qhi[mi] += __shfl_xor_sync(0xffffffffu, qhi[mi], m);
        }
    }
    if ((lane & 3) == 0) {
#pragma unroll
        for (int mi = 0; mi < 4; mi++) {
            int rowt = rbase + mi * 16 + (lane >> 2);
            red[nw * 128 + rowt]     = qlo[mi];
            red[nw * 128 + rowt + 8] = qhi[mi];
        }
    }
    __syncthreads();
    if (tid < 128) {
        float q = red[tid] + red[128 + tid] + red[256 + tid] + red[384 + tid];
        int r = r0 + tid;
        if (r < RV) {
            int b = r / LOUT, l = r - b * LOUT;
            g_Q[((size_t)k * BB + b) * LOUT + l] = q;
        }
    }
}

// ---------------- K4: losses (reference's flat-reshape softmax rows) ----------------
__global__ __launch_bounds__(256) void k_loss_part(const int* __restrict__ perm)
{
    const int k = blockIdx.x + 1;
    const int b = blockIdx.y;
    const int llen = LOUT - k;
    const float* Qk = g_Q + (size_t)(k - 1) * BB * LOUT;
    double acc = 0.0;
    for (int r = threadIdx.x; r < llen; r += 256) {
        int idx = 11 * r;
        int s = idx / llen;
        int i = idx - s * llen;
        float f[NNEG + 1];
#pragma unroll
        for (int j = 0; j <= NNEG; j++) {
            float v;
            if (s == 0) v = Qk[b * LOUT + k + i];
            else {
                int bb2 = (b - s) & (BB - 1);
                v = Qk[bb2 * LOUT + __ldg(&perm[k + i])];
            }
            f[j] = v;
            i++;
            if (i == llen) { i = 0; s++; }
        }
        float mx = f[0];
#pragma unroll
        for (int j = 1; j <= NNEG; j++) mx = fmaxf(mx, f[j]);
        float se = 0.0f, sf = 0.0f;
#pragma unroll
        for (int j = 0; j <= NNEG; j++) { se += __expf(f[j] - mx); sf += f[j]; }
        float lse = mx + __logf(se);
        acc += (double)((NNEG + 1) * lse - sf);
    }
    __shared__ double rsh[256];
    rsh[threadIdx.x] = acc;
    __syncthreads();
    for (int off = 128; off; off >>= 1) {
        if (threadIdx.x < off) rsh[threadIdx.x] += rsh[threadIdx.x + off];
        __syncthreads();
    }
    if (threadIdx.x == 0) g_part[(k - 1) * BB + b] = rsh[0];
}
__global__ __launch_bounds__(32) void k_loss_fin(float* __restrict__ out_losses)
{
    int kk = threadIdx.x;
    if (kk >= KST) return;
    int k = kk + 1;
    int llen = LOUT - k;
    double s = 0.0;
#pragma unroll
    for (int b = 0; b < BB; b++) s += g_part[kk * BB + b];
    out_losses[kk] = (float)(s / ((double)(llen - k) * BB));
}

// ---------------- launch ----------------
extern "C" void kernel_launch(void* const* d_in, const int* in_sizes, int n_in,
                              void* d_out, int out_size)
{
    const float* x      = (const float*)d_in[0];
    const float* conv_w = (const float*)d_in[1];
    const float* conv_b = (const float*)d_in[2];
    const float* gamma  = (const float*)d_in[3];
    const float* beta   = (const float*)d_in[4];
    const float* trw    = (const float*)d_in[5];
    const float* trb    = (const float*)d_in[6];
    const int*   perm   = (const int*)d_in[7];
    float* out = (float*)d_out;

    cudaFuncSetAttribute(k_gemm, cudaFuncAttributeMaxDynamicSharedMemorySize, SMEM_DYN);

    dim3 gs(8, BB);
    k_stats_p<<<gs, 256>>>(x, conv_w, conv_b);           // launch 1
    k_stats_f<<<1, 256>>>(gamma, beta);                  // launch 2 (+pad)

    dim3 gf(64, 18);                                     // 16 fuse + 2 S-prep rows
    k_fuse_w<<<gf, 256>>>(x, conv_w, conv_b, trw, out);  // launch 3

    dim3 gg(KST, NTILE);
    k_gemm<<<gg, 256, SMEM_DYN>>>(trb);                  // launch 4 <- profiled

    dim3 g4(KST, BB);
    k_loss_part<<<g4, 256>>>(perm);                      // launch 5
    k_loss_fin<<<1, 32>>>(out + (size_t)BB * CC * LOUT); // launch 6
}

// round 16
// speedup vs baseline: 1.2338x; 1.2338x over previous
#include <cuda_runtime.h>
#include <cuda_bf16.h>
#include <math.h>
#include <stdint.h>

#define BB    16
#define TT    10240
#define CC    256
#define KERN  10
#define STRD  5
#define LOUT  2047
#define KST   12
#define NNEG  10
#define EPSV  1e-5f
#define RV    32752          // B*LOUT valid rows
#define RP    32768          // padded rows (256 tiles x 128)
#define NTILE 256            // M-tiles of 128
#define NPART 128            // stats partials per channel (16 b x 8 ltiles)

// ---- GEMM smem: A kept per-chunk (full zhi tile), zlo prefetch, S reused.
#define OFF_A   0                         // 4 x 16384 = 65536 (zhi quarters)
#define OFF_ZLO 65536                     // 65536 (zlo quarters, same layout)
#define OFF_BHI 131072                    // 32768
#define OFF_BLO 163840                    // 32768
#define OFF_RED 196608                    // float red[4][128]
#define SMEM_DYN (OFF_RED + 2048)         // 198656 bytes -> 1 CTA/SM

// ---------------- device scratch (no allocation allowed) ----------------
__device__ __align__(16) float         g_scale[CC];
__device__ __align__(16) float         g_shift[CC];
__device__ __align__(16) double        g_sp1[CC * NPART];
__device__ __align__(16) double        g_sp2[CC * NPART];
__device__ __align__(16) float         g_Q[(size_t)KST * BB * LOUT];
__device__ __align__(16) double        g_part[KST * BB];
__device__ __align__(16) __nv_bfloat16 g_Zhi[(size_t)RP * CC];
__device__ __align__(16) __nv_bfloat16 g_Zlo[(size_t)RP * CC];
__device__ __align__(16) __nv_bfloat16 g_Shi[(size_t)KST * CC * CC];  // [k][n][c] = S[c][n], S=(W+W^T)/2
__device__ __align__(16) __nv_bfloat16 g_Slo[(size_t)KST * CC * CC];

// ---------------- helpers (baseline sm_80+ PTX only) ----------------
__device__ __forceinline__ uint32_t smem_u32(const void* p) {
    uint32_t a;
    asm("{ .reg .u64 t; cvta.to.shared.u64 t, %1; cvt.u32.u64 %0, t; }" : "=r"(a) : "l"(p));
    return a;
}
__device__ __forceinline__ void cp16(uint32_t dst, const void* src) {
    asm volatile("cp.async.cg.shared.global [%0], [%1], 16;" :: "r"(dst), "l"(src));
}
#define CP_COMMIT() asm volatile("cp.async.commit_group;" ::: "memory")
#define CP_WAIT(n)  asm volatile("cp.async.wait_group %0;" :: "n"(n) : "memory")

#define LDSM4(r0, r1, r2, r3, addr) \
    asm volatile("ldmatrix.sync.aligned.m8n8.x4.shared.b16 {%0,%1,%2,%3}, [%4];" \
        : "=r"(r0), "=r"(r1), "=r"(r2), "=r"(r3) : "r"(addr))

__device__ __forceinline__ uint32_t lds32(uint32_t a) {
    uint32_t v;
    asm("ld.shared.b32 %0, [%1];" : "=r"(v) : "r"(a));
    return v;
}
__device__ __forceinline__ float2 bf2f(uint32_t u) {
    __nv_bfloat162 t = *reinterpret_cast<__nv_bfloat162*>(&u);
    return make_float2(__bfloat162float(t.x), __bfloat162float(t.y));
}
__device__ __forceinline__ void mma16816(float* c, const uint32_t* a, const uint32_t* b) {
    asm volatile("mma.sync.aligned.m16n8k16.row.col.f32.bf16.bf16.f32 "
        "{%0,%1,%2,%3}, {%4,%5,%6,%7}, {%8,%9}, {%0,%1,%2,%3};"
        : "+f"(c[0]), "+f"(c[1]), "+f"(c[2]), "+f"(c[3])
        : "r"(a[0]), "r"(a[1]), "r"(a[2]), "r"(a[3]), "r"(b[0]), "r"(b[1]));
}

// ---------------- K1a: conv+relu partial stats, smem-staged x ----------------
__global__ __launch_bounds__(256) void k_stats_p(
    const float* __restrict__ x, const float* __restrict__ w,
    const float* __restrict__ bias)
{
    __shared__ float xs[256 * STRD + KERN];
    const int lt = blockIdx.x, b = blockIdx.y;
    const int l0 = lt * 256;
    const int cnt = (l0 + 256 <= LOUT) ? 256 : (LOUT - l0);
    const int base = l0 * STRD;
    for (int i = threadIdx.x; i < 256 * STRD + KERN; i += 256) {
        int g = base + i;
        xs[i] = (g < TT) ? x[(size_t)b * TT + g] : 0.0f;
    }
    __syncthreads();

    const int c = threadIdx.x;
    float wr[KERN];
#pragma unroll
    for (int i = 0; i < KERN; i++) wr[i] = __ldg(&w[c * KERN + i]);
    const float bc = __ldg(&bias[c]);
    double s1 = 0.0, s2 = 0.0;
    for (int l = 0; l < cnt; l++) {
        float h = bc;
#pragma unroll
        for (int i = 0; i < KERN; i++) h = fmaf(xs[l * STRD + i], wr[i], h);
        h = fmaxf(h, 0.0f);
        s1 += (double)h;
        s2 += (double)h * (double)h;
    }
    g_sp1[c * NPART + b * 8 + lt] = s1;
    g_sp2[c * NPART + b * 8 + lt] = s2;
}

// ---------------- K1b: finalize BN scale/shift + pad Z tail rows ----------------
__global__ __launch_bounds__(256) void k_stats_f(
    const float* __restrict__ gamma, const float* __restrict__ beta)
{
    int c = threadIdx.x;
    double s1 = 0.0, s2 = 0.0;
#pragma unroll 8
    for (int j = 0; j < NPART; j++) { s1 += g_sp1[c * NPART + j]; s2 += g_sp2[c * NPART + j]; }
    double N = (double)BB * LOUT;
    double mu = s1 / N;
    double var = s2 / N - mu * mu;
    double rs = 1.0 / sqrt(var + (double)EPSV);
    float sc = (float)((double)gamma[c] * rs);
    g_scale[c] = sc;
    g_shift[c] = beta[c] - (float)mu * sc;
    __nv_bfloat16 z0 = __float2bfloat16(0.0f);
#pragma unroll
    for (int r = 0; r < RP - RV; r++) {
        size_t o = (size_t)(RV + r) * CC + c;
        g_Zhi[o] = z0;
        g_Zlo[o] = z0;
    }
}

// ---------------- K2: fused conv+BN -> d_out + Z split  (+ S split, b>=16) ----
__global__ __launch_bounds__(256) void k_fuse_w(
    const float* __restrict__ x, const float* __restrict__ w,
    const float* __restrict__ bias, const float* __restrict__ trw,
    float* __restrict__ out)
{
    __shared__ float sh[168 + 256 * 33];
    const int tid = threadIdx.x;

    if (blockIdx.y < 16) {
        float* xs = sh;
        float* ht = sh + 168;                 // [256][33]
        const int l0 = blockIdx.x * 32;
        const int b  = blockIdx.y;

        const int base = l0 * STRD;
        for (int i = tid; i < 165; i += 256) {
            int g = base + i;
            xs[i] = (g < TT) ? x[(size_t)b * TT + g] : 0.0f;
        }
        __syncthreads();

        {   // thread = channel
            const int c = tid;
            float wr[KERN];
#pragma unroll
            for (int i = 0; i < KERN; i++) wr[i] = __ldg(&w[c * KERN + i]);
            const float bc = __ldg(&bias[c]);
            const float sc = g_scale[c], shi = g_shift[c];
#pragma unroll
            for (int l = 0; l < 32; l++) {
                float h = bc;
#pragma unroll
                for (int i = 0; i < KERN; i++) h = fmaf(xs[l * STRD + i], wr[i], h);
                h = fmaxf(h, 0.0f);
                ht[c * 33 + l] = fmaf(h, sc, shi);
            }
        }
        __syncthreads();

        {   // d_out[b,c,l] coalesced along l
            const int l = tid & 31;
            const int lg = l0 + l;
            if (lg < LOUT) {
#pragma unroll
                for (int j = 0; j < 32; j++) {
                    int c = (tid >> 5) + j * 8;
                    out[((size_t)b * CC + c) * LOUT + lg] = ht[c * 33 + l];
                }
            }
        }
        {   // Z arrays [r][c], c = tid coalesced
            const int c = tid;
#pragma unroll 4
            for (int l = 0; l < 32; l++) {
                int lg = l0 + l;
                if (lg >= LOUT) break;
                size_t r = (size_t)b * LOUT + lg;
                float v = ht[c * 33 + l];
                __nv_bfloat16 hi = __float2bfloat16(v);
                __nv_bfloat16 lo = __float2bfloat16(v - __bfloat162float(hi));
                g_Zhi[r * CC + c] = hi;
                g_Zlo[r * CC + c] = lo;
            }
        }
    } else {
        // S = (W + W^T)/2 transpose+split: 128 blocks x 6 tiles = 768 = 12k x 8 x 8
        float* t1 = sh;                       // [32][33]  W[c][n] tile
        float* t2 = sh + 32 * 33;             // [32][33]  W[n][c] tile
        const int idx = (blockIdx.y - 16) * 64 + blockIdx.x;
        for (int j = 0; j < 6; j++) {
            const int tno = idx * 6 + j;
            const int k = tno >> 6;
            const int rem = tno & 63;
            const int c0 = (rem >> 3) << 5, n0 = (rem & 7) << 5;
            const float* W = trw + (size_t)k * CC * CC;
            for (int i = tid; i < 32 * 32; i += 256) {
                int rr = i >> 5, cc2 = i & 31;
                t1[rr * 33 + cc2] = W[(size_t)(c0 + rr) * CC + n0 + cc2];
                t2[rr * 33 + cc2] = W[(size_t)(n0 + rr) * CC + c0 + cc2];
            }
            __syncthreads();
            for (int i = tid; i < 32 * 32; i += 256) {
                int nn = i >> 5, cc = i & 31;
                float v = 0.5f * (t1[cc * 33 + nn] + t2[nn * 33 + cc]);
                __nv_bfloat16 hi = __float2bfloat16(v);
                __nv_bfloat16 lo = __float2bfloat16(v - __bfloat162float(hi));
                size_t o = ((size_t)k * CC + n0 + nn) * CC + c0 + cc;
                g_Shi[o] = hi;
                g_Slo[o] = lo;
            }
            __syncthreads();
        }
    }
}

// ---------------- K3: HMMA 2-pass symmetric GEMM (serial R13 loop), smem epilogue --
// CTA = (k, m-tile 128). 8 warps 2Mx4N, warp tile 64x64.
// A quarters persist (full zhi tile in smem); zlo prefetched in bulk; S reused/chunk.
// U = zhi^T S.  Q = U.(zhi + 2*zlo) + b.(zhi + zlo).
__global__ __launch_bounds__(256) void k_gemm(const float* __restrict__ trb)
{
    extern __shared__ char smem[];
    const uint32_t sb = smem_u32(smem);
    const int tid  = threadIdx.x;
    const int lane = tid & 31;
    const int w    = tid >> 5;
    const int mw   = w >> 2, nw = w & 3;
    const int k    = blockIdx.x;
    const int mt   = blockIdx.y;
    const int r0   = mt * 128;
    const int rbase = mw * 64, nbase = nw * 64;

    const __nv_bfloat16* Ah = g_Zhi + (size_t)r0 * CC;
    const __nv_bfloat16* Zl = g_Zlo + (size_t)r0 * CC;
    const __nv_bfloat16* Bh = g_Shi + (size_t)k * CC * CC;
    const __nv_bfloat16* Bl = g_Slo + (size_t)k * CC * CC;

    // bulk zlo prefetch: all 4 column-quarters (group 1)
#pragma unroll
    for (int t = 0; t < 16; t++) {
        int i = tid + t * 256;               // 0..4095
        int q = i >> 10;
        int row = (i >> 3) & 127;
        int u = i & 7;
        uint32_t d = (uint32_t)(q * 16384 + row * 128 + ((u ^ (row & 7)) << 4));
        cp16(sb + OFF_ZLO + d, Zl + (size_t)row * CC + q * 64 + u * 8);
    }
    CP_COMMIT();

    auto load_chunk = [&](int kc) {
        const int co = kc * 64;
#pragma unroll
        for (int t = 0; t < 4; t++) {        // A -> quarter kc (1024 ops)
            int i = tid + t * 256;
            int row = i >> 3, u = i & 7;
            uint32_t d = (uint32_t)(row * 128 + ((u ^ (row & 7)) << 4));
            cp16(sb + OFF_A + kc * 16384 + d, Ah + (size_t)row * CC + co + u * 8);
        }
#pragma unroll
        for (int t = 0; t < 8; t++) {        // S: 256 rows (2048 ops each)
            int i = tid + t * 256;
            int row = i >> 3, u = i & 7;
            uint32_t d = (uint32_t)(row * 128 + ((u ^ (row & 7)) << 4));
            cp16(sb + OFF_BHI + d, Bh + (size_t)row * CC + co + u * 8);
            cp16(sb + OFF_BLO + d, Bl + (size_t)row * CC + co + u * 8);
        }
        CP_COMMIT();
    };

    float c[4][8][4];
#pragma unroll
    for (int mi = 0; mi < 4; mi++)
#pragma unroll
        for (int ni = 0; ni < 8; ni++)
#pragma unroll
            for (int j = 0; j < 4; j++) c[mi][ni][j] = 0.0f;

    // per-lane ldmatrix row bases (128B rows, XOR swizzle)
    const uint32_t aRow = (uint32_t)(rbase + (lane & 15));
    const uint32_t rmA  = aRow & 7;
    const uint32_t hiA  = (uint32_t)(lane >> 4);
    const uint32_t aBase = (uint32_t)(aRow * 128);
    const uint32_t bRow = (uint32_t)(nbase + (lane & 7) + ((lane >> 4) << 3));
    const uint32_t rmB  = (uint32_t)(lane & 7);
    const uint32_t hiB  = (uint32_t)((lane >> 3) & 1);
    const uint32_t bBase = (uint32_t)(bRow * 128);

    for (int kc = 0; kc < 4; kc++) {
        __syncthreads();                     // S buffers free
        load_chunk(kc);
        CP_WAIT(0);
        __syncthreads();

        const uint32_t aQ = sb + OFF_A + kc * 16384;
#pragma unroll
        for (int ks = 0; ks < 4; ks++) {
            const uint32_t colA = ((((uint32_t)(ks << 1) | hiA) ^ rmA) << 4);
            const uint32_t colB = ((((uint32_t)(ks << 1) | hiB) ^ rmB) << 4);
            const uint32_t pAH = aQ + aBase + colA;
            const uint32_t pBH = sb + OFF_BHI + bBase + colB;
            const uint32_t pBL = sb + OFF_BLO + bBase + colB;

            uint32_t aH[4][4], bH[8][2];
#pragma unroll
            for (int mi = 0; mi < 4; mi++)
                LDSM4(aH[mi][0], aH[mi][1], aH[mi][2], aH[mi][3], pAH + mi * 2048);
#pragma unroll
            for (int p = 0; p < 4; p++)
                LDSM4(bH[2 * p][0], bH[2 * p][1], bH[2 * p + 1][0], bH[2 * p + 1][1],
                      pBH + p * 2048);
            // pass 0: zhi * Shi
#pragma unroll
            for (int mi = 0; mi < 4; mi++)
#pragma unroll
                for (int ni = 0; ni < 8; ni++) mma16816(c[mi][ni], aH[mi], bH[ni]);
            // pass 1: zhi * Slo
            {
                uint32_t bL[8][2];
#pragma unroll
                for (int p = 0; p < 4; p++)
                    LDSM4(bL[2 * p][0], bL[2 * p][1], bL[2 * p + 1][0], bL[2 * p + 1][1],
                          pBL + p * 2048);
#pragma unroll
                for (int mi = 0; mi < 4; mi++)
#pragma unroll
                    for (int ni = 0; ni < 8; ni++) mma16816(c[mi][ni], aH[mi], bL[ni]);
            }
        }
    }

    // ---- epilogue (all smem): Q[r] = sum_n U*(zhi+2*zlo) + b*(zhi+zlo)
    float2 bias[8];
#pragma unroll
    for (int ni = 0; ni < 8; ni++)
        bias[ni] = __ldg((const float2*)&trb[k * CC + nbase + ni * 8 + (lane & 3) * 2]);

    // warp nw reads cols nbase..nbase+63 = quarter nw; unit within row = ni exactly.
    const uint32_t zhiB = sb + OFF_A   + (uint32_t)nw * 16384;
    const uint32_t zloB = sb + OFF_ZLO + (uint32_t)nw * 16384;
    const uint32_t pm   = (uint32_t)(lane >> 2);                 // row & 7
    const uint32_t rOff = (uint32_t)((rbase + (lane >> 2)) * 128 + (lane & 3) * 4);

    float* red = (float*)(smem + OFF_RED);
    float qlo[4], qhi[4];
#pragma unroll
    for (int mi = 0; mi < 4; mi++) { qlo[mi] = 0.0f; qhi[mi] = 0.0f; }
#pragma unroll
    for (int mi = 0; mi < 4; mi++) {
        const uint32_t bmi = rOff + mi * 2048;
#pragma unroll
        for (int ni = 0; ni < 8; ni++) {
            const uint32_t a1 = bmi + (((uint32_t)ni ^ pm) << 4);
            float2 h0 = bf2f(lds32(zhiB + a1));
            float2 h1 = bf2f(lds32(zhiB + a1 + 1024));            // +8 rows
            float2 l0 = bf2f(lds32(zloB + a1));
            float2 l1 = bf2f(lds32(zloB + a1 + 1024));
            qlo[mi] = fmaf(c[mi][ni][0], fmaf(2.0f, l0.x, h0.x), qlo[mi]);
            qlo[mi] = fmaf(c[mi][ni][1], fmaf(2.0f, l0.y, h0.y), qlo[mi]);
            qhi[mi] = fmaf(c[mi][ni][2], fmaf(2.0f, l1.x, h1.x), qhi[mi]);
            qhi[mi] = fmaf(c[mi][ni][3], fmaf(2.0f, l1.y, h1.y), qhi[mi]);
            qlo[mi] = fmaf(bias[ni].x, h0.x + l0.x, qlo[mi]);
            qlo[mi] = fmaf(bias[ni].y, h0.y + l0.y, qlo[mi]);
            qhi[mi] = fmaf(bias[ni].x, h1.x + l1.x, qhi[mi]);
            qhi[mi] = fmaf(bias[ni].y, h1.y + l1.y, qhi[mi]);
        }
    }
#pragma unroll
    for (int m = 1; m <= 2; m <<= 1) {
#pragma unroll
        for (int mi = 0; mi < 4; mi++) {
            qlo[mi] += __shfl_xor_sync(0xffffffffu, qlo[mi], m);
            qhi[mi] += __shfl_xor_sync(0xffffffffu, qhi[mi], m);
        }
    }
    if ((lane & 3) == 0) {
#pragma unroll
        for (int mi = 0; mi < 4; mi++) {
            int rowt = rbase + mi * 16 + (lane >> 2);
            red[nw * 128 + rowt]     = qlo[mi];
            red[nw * 128 + rowt + 8] = qhi[mi];
        }
    }
    __syncthreads();
    if (tid < 128) {
        float q = red[tid] + red[128 + tid] + red[256 + tid] + red[384 + tid];
        int r = r0 + tid;
        if (r < RV) {
            int b = r / LOUT, l = r - b * LOUT;
            g_Q[((size_t)k * BB + b) * LOUT + l] = q;
        }
    }
}

// ---------------- K4: losses (reference's flat-reshape softmax rows) ----------------
__global__ __launch_bounds__(256) void k_loss_part(const int* __restrict__ perm)
{
    const int k = blockIdx.x + 1;
    const int b = blockIdx.y;
    const int llen = LOUT - k;
    const float* Qk = g_Q + (size_t)(k - 1) * BB * LOUT;
    double acc = 0.0;
    for (int r = threadIdx.x; r < llen; r += 256) {
        int idx = 11 * r;
        int s = idx / llen;
        int i = idx - s * llen;
        float f[NNEG + 1];
#pragma unroll
        for (int j = 0; j <= NNEG; j++) {
            float v;
            if (s == 0) v = Qk[b * LOUT + k + i];
            else {
                int bb2 = (b - s) & (BB - 1);
                v = Qk[bb2 * LOUT + __ldg(&perm[k + i])];
            }
            f[j] = v;
            i++;
            if (i == llen) { i = 0; s++; }
        }
        float mx = f[0];
#pragma unroll
        for (int j = 1; j <= NNEG; j++) mx = fmaxf(mx, f[j]);
        float se = 0.0f, sf = 0.0f;
#pragma unroll
        for (int j = 0; j <= NNEG; j++) { se += __expf(f[j] - mx); sf += f[j]; }
        float lse = mx + __logf(se);
        acc += (double)((NNEG + 1) * lse - sf);
    }
    __shared__ double rsh[256];
    rsh[threadIdx.x] = acc;
    __syncthreads();
    for (int off = 128; off; off >>= 1) {
        if (threadIdx.x < off) rsh[threadIdx.x] += rsh[threadIdx.x + off];
        __syncthreads();
    }
    if (threadIdx.x == 0) g_part[(k - 1) * BB + b] = rsh[0];
}
__global__ __launch_bounds__(32) void k_loss_fin(float* __restrict__ out_losses)
{
    int kk = threadIdx.x;
    if (kk >= KST) return;
    int k = kk + 1;
    int llen = LOUT - k;
    double s = 0.0;
#pragma unroll
    for (int b = 0; b < BB; b++) s += g_part[kk * BB + b];
    out_losses[kk] = (float)(s / ((double)(llen - k) * BB));
}

// ---------------- launch ----------------
extern "C" void kernel_launch(void* const* d_in, const int* in_sizes, int n_in,
                              void* d_out, int out_size)
{
    const float* x      = (const float*)d_in[0];
    const float* conv_w = (const float*)d_in[1];
    const float* conv_b = (const float*)d_in[2];
    const float* gamma  = (const float*)d_in[3];
    const float* beta   = (const float*)d_in[4];
    const float* trw    = (const float*)d_in[5];
    const float* trb    = (const float*)d_in[6];
    const int*   perm   = (const int*)d_in[7];
    float* out = (float*)d_out;

    cudaFuncSetAttribute(k_gemm, cudaFuncAttributeMaxDynamicSharedMemorySize, SMEM_DYN);

    dim3 gs(8, BB);
    k_stats_p<<<gs, 256>>>(x, conv_w, conv_b);           // launch 1
    k_stats_f<<<1, 256>>>(gamma, beta);                  // launch 2 (+pad)

    dim3 gf(64, 18);                                     // 16 fuse + 2 S-prep rows
    k_fuse_w<<<gf, 256>>>(x, conv_w, conv_b, trw, out);  // launch 3

    dim3 gg(KST, NTILE);
    k_gemm<<<gg, 256, SMEM_DYN>>>(trb);                  // launch 4 <- profiled

    dim3 g4(KST, BB);
    k_loss_part<<<g4, 256>>>(perm);                      // launch 5
    k_loss_fin<<<1, 32>>>(out + (size_t)BB * CC * LOUT); // launch 6
}

// round 17
// speedup vs baseline: 1.2639x; 1.0244x over previous
#include <cuda_runtime.h>
#include <cuda_bf16.h>
#include <math.h>
#include <stdint.h>

#define BB    16
#define TT    10240
#define CC    256
#define KERN  10
#define STRD  5
#define LOUT  2047
#define KST   12
#define NNEG  10
#define EPSV  1e-5f
#define RV    32752          // B*LOUT valid rows
#define RP    32768          // padded rows (256 tiles x 128)
#define NTILE 256            // M-tiles of 128
#define NPART 128            // stats partials per channel (16 b x 8 ltiles)

// ---- GEMM smem: A quarters persist; S double-buffered; zlo lands in stage0 at end.
#define OFF_A   0                         // 4 x 16384 = 65536 (zhi quarters)
#define OFF_S0  65536                     // stage0: Shi @ +0, Slo @ +32768 (64KB)
#define OFF_S1  131072                    // stage1: 64KB
#define SSTG    65536
#define OFF_RED 196608                    // float red[4][128]
#define SMEM_DYN (OFF_RED + 2048)         // 198656 bytes -> 1 CTA/SM

// ---------------- device scratch (no allocation allowed) ----------------
__device__ __align__(16) float         g_scale[CC];
__device__ __align__(16) float         g_shift[CC];
__device__ __align__(16) double        g_sp1[CC * NPART];
__device__ __align__(16) double        g_sp2[CC * NPART];
__device__ __align__(16) float         g_Q[(size_t)KST * BB * LOUT];
__device__ __align__(16) double        g_part[KST * BB];
__device__ __align__(16) __nv_bfloat16 g_Zhi[(size_t)RP * CC];
__device__ __align__(16) __nv_bfloat16 g_Zlo[(size_t)RP * CC];
__device__ __align__(16) __nv_bfloat16 g_Shi[(size_t)KST * CC * CC];  // [k][n][c] = S[c][n], S=(W+W^T)/2
__device__ __align__(16) __nv_bfloat16 g_Slo[(size_t)KST * CC * CC];

// ---------------- helpers (baseline sm_80+ PTX only) ----------------
__device__ __forceinline__ uint32_t smem_u32(const void* p) {
    uint32_t a;
    asm("{ .reg .u64 t; cvta.to.shared.u64 t, %1; cvt.u32.u64 %0, t; }" : "=r"(a) : "l"(p));
    return a;
}
__device__ __forceinline__ void cp16(uint32_t dst, const void* src) {
    asm volatile("cp.async.cg.shared.global [%0], [%1], 16;" :: "r"(dst), "l"(src));
}
#define CP_COMMIT() asm volatile("cp.async.commit_group;" ::: "memory")
#define CP_WAIT(n)  asm volatile("cp.async.wait_group %0;" :: "n"(n) : "memory")

#define LDSM4(r0, r1, r2, r3, addr) \
    asm volatile("ldmatrix.sync.aligned.m8n8.x4.shared.b16 {%0,%1,%2,%3}, [%4];" \
        : "=r"(r0), "=r"(r1), "=r"(r2), "=r"(r3) : "r"(addr))

__device__ __forceinline__ uint32_t lds32(uint32_t a) {
    uint32_t v;
    asm("ld.shared.b32 %0, [%1];" : "=r"(v) : "r"(a));
    return v;
}
__device__ __forceinline__ float2 bf2f(uint32_t u) {
    __nv_bfloat162 t = *reinterpret_cast<__nv_bfloat162*>(&u);
    return make_float2(__bfloat162float(t.x), __bfloat162float(t.y));
}
__device__ __forceinline__ void mma16816(float* c, const uint32_t* a, const uint32_t* b) {
    asm volatile("mma.sync.aligned.m16n8k16.row.col.f32.bf16.bf16.f32 "
        "{%0,%1,%2,%3}, {%4,%5,%6,%7}, {%8,%9}, {%0,%1,%2,%3};"
        : "+f"(c[0]), "+f"(c[1]), "+f"(c[2]), "+f"(c[3])
        : "r"(a[0]), "r"(a[1]), "r"(a[2]), "r"(a[3]), "r"(b[0]), "r"(b[1]));
}

// ---------------- K1a: conv+relu partial stats, smem-staged x ----------------
__global__ __launch_bounds__(256) void k_stats_p(
    const float* __restrict__ x, const float* __restrict__ w,
    const float* __restrict__ bias)
{
    __shared__ float xs[256 * STRD + KERN];
    const int lt = blockIdx.x, b = blockIdx.y;
    const int l0 = lt * 256;
    const int cnt = (l0 + 256 <= LOUT) ? 256 : (LOUT - l0);
    const int base = l0 * STRD;
    for (int i = threadIdx.x; i < 256 * STRD + KERN; i += 256) {
        int g = base + i;
        xs[i] = (g < TT) ? x[(size_t)b * TT + g] : 0.0f;
    }
    __syncthreads();

    const int c = threadIdx.x;
    float wr[KERN];
#pragma unroll
    for (int i = 0; i < KERN; i++) wr[i] = __ldg(&w[c * KERN + i]);
    const float bc = __ldg(&bias[c]);
    double s1 = 0.0, s2 = 0.0;
    for (int l = 0; l < cnt; l++) {
        float h = bc;
#pragma unroll
        for (int i = 0; i < KERN; i++) h = fmaf(xs[l * STRD + i], wr[i], h);
        h = fmaxf(h, 0.0f);
        s1 += (double)h;
        s2 += (double)h * (double)h;
    }
    g_sp1[c * NPART + b * 8 + lt] = s1;
    g_sp2[c * NPART + b * 8 + lt] = s2;
}

// ---------------- K1b: finalize BN scale/shift + pad Z tail rows ----------------
__global__ __launch_bounds__(256) void k_stats_f(
    const float* __restrict__ gamma, const float* __restrict__ beta)
{
    int c = threadIdx.x;
    double s1 = 0.0, s2 = 0.0;
#pragma unroll 8
    for (int j = 0; j < NPART; j++) { s1 += g_sp1[c * NPART + j]; s2 += g_sp2[c * NPART + j]; }
    double N = (double)BB * LOUT;
    double mu = s1 / N;
    double var = s2 / N - mu * mu;
    double rs = 1.0 / sqrt(var + (double)EPSV);
    float sc = (float)((double)gamma[c] * rs);
    g_scale[c] = sc;
    g_shift[c] = beta[c] - (float)mu * sc;
    __nv_bfloat16 z0 = __float2bfloat16(0.0f);
#pragma unroll
    for (int r = 0; r < RP - RV; r++) {
        size_t o = (size_t)(RV + r) * CC + c;
        g_Zhi[o] = z0;
        g_Zlo[o] = z0;
    }
}

// ---------------- K2: fused conv+BN -> d_out + Z split  (+ S split, b>=16) ----
__global__ __launch_bounds__(256) void k_fuse_w(
    const float* __restrict__ x, const float* __restrict__ w,
    const float* __restrict__ bias, const float* __restrict__ trw,
    float* __restrict__ out)
{
    __shared__ float sh[168 + 256 * 33];
    const int tid = threadIdx.x;

    if (blockIdx.y < 16) {
        float* xs = sh;
        float* ht = sh + 168;                 // [256][33]
        const int l0 = blockIdx.x * 32;
        const int b  = blockIdx.y;

        const int base = l0 * STRD;
        for (int i = tid; i < 165; i += 256) {
            int g = base + i;
            xs[i] = (g < TT) ? x[(size_t)b * TT + g] : 0.0f;
        }
        __syncthreads();

        {   // thread = channel
            const int c = tid;
            float wr[KERN];
#pragma unroll
            for (int i = 0; i < KERN; i++) wr[i] = __ldg(&w[c * KERN + i]);
            const float bc = __ldg(&bias[c]);
            const float sc = g_scale[c], shi = g_shift[c];
#pragma unroll
            for (int l = 0; l < 32; l++) {
                float h = bc;
#pragma unroll
                for (int i = 0; i < KERN; i++) h = fmaf(xs[l * STRD + i], wr[i], h);
                h = fmaxf(h, 0.0f);
                ht[c * 33 + l] = fmaf(h, sc, shi);
            }
        }
        __syncthreads();

        {   // d_out[b,c,l] coalesced along l
            const int l = tid & 31;
            const int lg = l0 + l;
            if (lg < LOUT) {
#pragma unroll
                for (int j = 0; j < 32; j++) {
                    int c = (tid >> 5) + j * 8;
                    out[((size_t)b * CC + c) * LOUT + lg] = ht[c * 33 + l];
                }
            }
        }
        {   // Z arrays [r][c], c = tid coalesced
            const int c = tid;
#pragma unroll 4
            for (int l = 0; l < 32; l++) {
                int lg = l0 + l;
                if (lg >= LOUT) break;
                size_t r = (size_t)b * LOUT + lg;
                float v = ht[c * 33 + l];
                __nv_bfloat16 hi = __float2bfloat16(v);
                __nv_bfloat16 lo = __float2bfloat16(v - __bfloat162float(hi));
                g_Zhi[r * CC + c] = hi;
                g_Zlo[r * CC + c] = lo;
            }
        }
    } else {
        // S = (W + W^T)/2 transpose+split: 128 blocks x 6 tiles = 768 = 12k x 8 x 8
        float* t1 = sh;                       // [32][33]  W[c][n] tile
        float* t2 = sh + 32 * 33;             // [32][33]  W[n][c] tile
        const int idx = (blockIdx.y - 16) * 64 + blockIdx.x;
        for (int j = 0; j < 6; j++) {
            const int tno = idx * 6 + j;
            const int k = tno >> 6;
            const int rem = tno & 63;
            const int c0 = (rem >> 3) << 5, n0 = (rem & 7) << 5;
            const float* W = trw + (size_t)k * CC * CC;
            for (int i = tid; i < 32 * 32; i += 256) {
                int rr = i >> 5, cc2 = i & 31;
                t1[rr * 33 + cc2] = W[(size_t)(c0 + rr) * CC + n0 + cc2];
                t2[rr * 33 + cc2] = W[(size_t)(n0 + rr) * CC + c0 + cc2];
            }
            __syncthreads();
            for (int i = tid; i < 32 * 32; i += 256) {
                int nn = i >> 5, cc = i & 31;
                float v = 0.5f * (t1[cc * 33 + nn] + t2[nn * 33 + cc]);
                __nv_bfloat16 hi = __float2bfloat16(v);
                __nv_bfloat16 lo = __float2bfloat16(v - __bfloat162float(hi));
                size_t o = ((size_t)k * CC + n0 + nn) * CC + c0 + cc;
                g_Shi[o] = hi;
                g_Slo[o] = lo;
            }
            __syncthreads();
        }
    }
}

// ---------------- K3: HMMA 2-pass symmetric GEMM, S double-buffered ----------------
// CTA = (k, m-tile 128). 8 warps 2Mx4N, warp tile 64x64.
// A quarters persist (full zhi tile); S chunks ping-pong stage0/1; zlo bulk-loads
// into stage0 during last chunk's compute. Epilogue entirely from smem.
// U = zhi^T S.  Q = U.(zhi + 2*zlo) + b.(zhi + zlo).
__global__ __launch_bounds__(256) void k_gemm(const float* __restrict__ trb)
{
    extern __shared__ char smem[];
    const uint32_t sb = smem_u32(smem);
    const int tid  = threadIdx.x;
    const int lane = tid & 31;
    const int w    = tid >> 5;
    const int mw   = w >> 2, nw = w & 3;
    const int k    = blockIdx.x;
    const int mt   = blockIdx.y;
    const int r0   = mt * 128;
    const int rbase = mw * 64, nbase = nw * 64;

    const __nv_bfloat16* Ah = g_Zhi + (size_t)r0 * CC;
    const __nv_bfloat16* Zl = g_Zlo + (size_t)r0 * CC;
    const __nv_bfloat16* Bh = g_Shi + (size_t)k * CC * CC;
    const __nv_bfloat16* Bl = g_Slo + (size_t)k * CC * CC;

    // load chunk kc: A quarter kc + S chunk (hi+lo) into stage kc&1; one commit group
    auto load_chunk = [&](int kc) {
        const int co = kc * 64;
        const uint32_t st = sb + OFF_S0 + (uint32_t)(kc & 1) * SSTG;
#pragma unroll
        for (int t = 0; t < 4; t++) {        // A -> quarter kc (1024 ops)
            int i = tid + t * 256;
            int row = i >> 3, u = i & 7;
            uint32_t d = (uint32_t)(row * 128 + ((u ^ (row & 7)) << 4));
            cp16(sb + OFF_A + kc * 16384 + d, Ah + (size_t)row * CC + co + u * 8);
        }
#pragma unroll
        for (int t = 0; t < 8; t++) {        // S: 256 rows (2048 ops each of hi/lo)
            int i = tid + t * 256;
            int row = i >> 3, u = i & 7;
            uint32_t d = (uint32_t)(row * 128 + ((u ^ (row & 7)) << 4));
            cp16(st + d,         Bh + (size_t)row * CC + co + u * 8);
            cp16(st + 32768 + d, Bl + (size_t)row * CC + co + u * 8);
        }
        CP_COMMIT();
    };
    // bulk zlo load into stage0 (after chunk2's data there is consumed)
    auto load_zlo = [&]() {
#pragma unroll
        for (int t = 0; t < 16; t++) {
            int i = tid + t * 256;           // 0..4095
            int q = i >> 10;
            int row = (i >> 3) & 127;
            int u = i & 7;
            uint32_t d = (uint32_t)(q * 16384 + row * 128 + ((u ^ (row & 7)) << 4));
            cp16(sb + OFF_S0 + d, Zl + (size_t)row * CC + q * 64 + u * 8);
        }
        CP_COMMIT();
    };

    float c[4][8][4];
#pragma unroll
    for (int mi = 0; mi < 4; mi++)
#pragma unroll
        for (int ni = 0; ni < 8; ni++)
#pragma unroll
            for (int j = 0; j < 4; j++) c[mi][ni][j] = 0.0f;

    // per-lane ldmatrix row bases (128B rows, XOR swizzle)
    const uint32_t aRow = (uint32_t)(rbase + (lane & 15));
    const uint32_t rmA  = aRow & 7;
    const uint32_t hiA  = (uint32_t)(lane >> 4);
    const uint32_t aBase = (uint32_t)(aRow * 128);
    const uint32_t bRow = (uint32_t)(nbase + (lane & 7) + ((lane >> 4) << 3));
    const uint32_t rmB  = (uint32_t)(lane & 7);
    const uint32_t hiB  = (uint32_t)((lane >> 3) & 1);
    const uint32_t bBase = (uint32_t)(bRow * 128);

    load_chunk(0);

    for (int kc = 0; kc < 4; kc++) {
        CP_WAIT(0);                          // chunk kc resident
        __syncthreads();                     // all warps past compute(kc-1); stage reuse safe
        if (kc < 3) load_chunk(kc + 1);      // overlaps compute(kc)
        else        load_zlo();              // into stage0 (chunk2 consumed)

        const uint32_t aQ = sb + OFF_A + kc * 16384;
        const uint32_t st = sb + OFF_S0 + (uint32_t)(kc & 1) * SSTG;
#pragma unroll
        for (int ks = 0; ks < 4; ks++) {
            const uint32_t colA = ((((uint32_t)(ks << 1) | hiA) ^ rmA) << 4);
            const uint32_t colB = ((((uint32_t)(ks << 1) | hiB) ^ rmB) << 4);
            const uint32_t pAH = aQ + aBase + colA;
            const uint32_t pBH = st + bBase + colB;
            const uint32_t pBL = st + 32768 + bBase + colB;

            uint32_t aH[4][4], bH[8][2];
#pragma unroll
            for (int mi = 0; mi < 4; mi++)
                LDSM4(aH[mi][0], aH[mi][1], aH[mi][2], aH[mi][3], pAH + mi * 2048);
#pragma unroll
            for (int p = 0; p < 4; p++)
                LDSM4(bH[2 * p][0], bH[2 * p][1], bH[2 * p + 1][0], bH[2 * p + 1][1],
                      pBH + p * 2048);
            // pass 0: zhi * Shi
#pragma unroll
            for (int mi = 0; mi < 4; mi++)
#pragma unroll
                for (int ni = 0; ni < 8; ni++) mma16816(c[mi][ni], aH[mi], bH[ni]);
            // pass 1: zhi * Slo
            {
                uint32_t bL[8][2];
#pragma unroll
                for (int p = 0; p < 4; p++)
                    LDSM4(bL[2 * p][0], bL[2 * p][1], bL[2 * p + 1][0], bL[2 * p + 1][1],
                          pBL + p * 2048);
#pragma unroll
                for (int mi = 0; mi < 4; mi++)
#pragma unroll
                    for (int ni = 0; ni < 8; ni++) mma16816(c[mi][ni], aH[mi], bL[ni]);
            }
        }
    }

    // ---- epilogue (all smem): Q[r] = sum_n U*(zhi+2*zlo) + b*(zhi+zlo)
    CP_WAIT(0);                              // zlo resident
    __syncthreads();

    float2 bias[8];
#pragma unroll
    for (int ni = 0; ni < 8; ni++)
        bias[ni] = __ldg((const float2*)&trb[k * CC + nbase + ni * 8 + (lane & 3) * 2]);

    // warp nw reads cols nbase..nbase+63 = quarter nw; unit within row = ni exactly.
    const uint32_t zhiB = sb + OFF_A  + (uint32_t)nw * 16384;
    const uint32_t zloB = sb + OFF_S0 + (uint32_t)nw * 16384;
    const uint32_t pm   = (uint32_t)(lane >> 2);                 // row & 7
    const uint32_t rOff = (uint32_t)((rbase + (lane >> 2)) * 128 + (lane & 3) * 4);

    float* red = (float*)(smem + OFF_RED);
    float qlo[4], qhi[4];
#pragma unroll
    for (int mi = 0; mi < 4; mi++) { qlo[mi] = 0.0f; qhi[mi] = 0.0f; }
#pragma unroll
    for (int mi = 0; mi < 4; mi++) {
        const uint32_t bmi = rOff + mi * 2048;
#pragma unroll
        for (int ni = 0; ni < 8; ni++) {
            const uint32_t a1 = bmi + (((uint32_t)ni ^ pm) << 4);
            float2 h0 = bf2f(lds32(zhiB + a1));
            float2 h1 = bf2f(lds32(zhiB + a1 + 1024));            // +8 rows
            float2 l0 = bf2f(lds32(zloB + a1));
            float2 l1 = bf2f(lds32(zloB + a1 + 1024));
            qlo[mi] = fmaf(c[mi][ni][0], fmaf(2.0f, l0.x, h0.x), qlo[mi]);
            qlo[mi] = fmaf(c[mi][ni][1], fmaf(2.0f, l0.y, h0.y), qlo[mi]);
            qhi[mi] = fmaf(c[mi][ni][2], fmaf(2.0f, l1.x, h1.x), qhi[mi]);
            qhi[mi] = fmaf(c[mi][ni][3], fmaf(2.0f, l1.y, h1.y), qhi[mi]);
            qlo[mi] = fmaf(bias[ni].x, h0.x + l0.x, qlo[mi]);
            qlo[mi] = fmaf(bias[ni].y, h0.y + l0.y, qlo[mi]);
            qhi[mi] = fmaf(bias[ni].x, h1.x + l1.x, qhi[mi]);
            qhi[mi] = fmaf(bias[ni].y, h1.y + l1.y, qhi[mi]);
        }
    }
#pragma unroll
    for (int m = 1; m <= 2; m <<= 1) {
#pragma unroll
        for (int mi = 0; mi < 4; mi++) {
            qlo[mi] += __shfl_xor_sync(0xffffffffu, qlo[mi], m);
            qhi[mi] += __shfl_xor_sync(0xffffffffu, qhi[mi], m);
        }
    }
    if ((lane & 3) == 0) {
#pragma unroll
        for (int mi = 0; mi < 4; mi++) {
            int rowt = rbase + mi * 16 + (lane >> 2);
            red[nw * 128 + rowt]     = qlo[mi];
            red[nw * 128 + rowt + 8] = qhi[mi];
        }
    }
    __syncthreads();
    if (tid < 128) {
        float q = red[tid] + red[128 + tid] + red[256 + tid] + red[384 + tid];
        int r = r0 + tid;
        if (r < RV) {
            int b = r / LOUT, l = r - b * LOUT;
            g_Q[((size_t)k * BB + b) * LOUT + l] = q;
        }
    }
}

// ---------------- K4: losses (reference's flat-reshape softmax rows) ----------------
__global__ __launch_bounds__(256) void k_loss_part(const int* __restrict__ perm)
{
    const int k = blockIdx.x + 1;
    const int b = blockIdx.y;
    const int llen = LOUT - k;
    const float* Qk = g_Q + (size_t)(k - 1) * BB * LOUT;
    double acc = 0.0;
    for (int r = threadIdx.x; r < llen; r += 256) {
        int idx = 11 * r;
        int s = idx / llen;
        int i = idx - s * llen;
        float f[NNEG + 1];
#pragma unroll
        for (int j = 0; j <= NNEG; j++) {
            float v;
            if (s == 0) v = Qk[b * LOUT + k + i];
            else {
                int bb2 = (b - s) & (BB - 1);
                v = Qk[bb2 * LOUT + __ldg(&perm[k + i])];
            }
            f[j] = v;
            i++;
            if (i == llen) { i = 0; s++; }
        }
        float mx = f[0];
#pragma unroll
        for (int j = 1; j <= NNEG; j++) mx = fmaxf(mx, f[j]);
        float se = 0.0f, sf = 0.0f;
#pragma unroll
        for (int j = 0; j <= NNEG; j++) { se += __expf(f[j] - mx); sf += f[j]; }
        float lse = mx + __logf(se);
        acc += (double)((NNEG + 1) * lse - sf);
    }
    __shared__ double rsh[256];
    rsh[threadIdx.x] = acc;
    __syncthreads();
    for (int off = 128; off; off >>= 1) {
        if (threadIdx.x < off) rsh[threadIdx.x] += rsh[threadIdx.x + off];
        __syncthreads();
    }
    if (threadIdx.x == 0) g_part[(k - 1) * BB + b] = rsh[0];
}
__global__ __launch_bounds__(32) void k_loss_fin(float* __restrict__ out_losses)
{
    int kk = threadIdx.x;
    if (kk >= KST) return;
    int k = kk + 1;
    int llen = LOUT - k;
    double s = 0.0;
#pragma unroll
    for (int b = 0; b < BB; b++) s += g_part[kk * BB + b];
    out_losses[kk] = (float)(s / ((double)(llen - k) * BB));
}

// ---------------- launch ----------------
extern "C" void kernel_launch(void* const* d_in, const int* in_sizes, int n_in,
                              void* d_out, int out_size)
{
    const float* x      = (const float*)d_in[0];
    const float* conv_w = (const float*)d_in[1];
    const float* conv_b = (const float*)d_in[2];
    const float* gamma  = (const float*)d_in[3];
    const float* beta   = (const float*)d_in[4];
    const float* trw    = (const float*)d_in[5];
    const float* trb    = (const float*)d_in[6];
    const int*   perm   = (const int*)d_in[7];
    float* out = (float*)d_out;

    cudaFuncSetAttribute(k_gemm, cudaFuncAttributeMaxDynamicSharedMemorySize, SMEM_DYN);

    dim3 gs(8, BB);
    k_stats_p<<<gs, 256>>>(x, conv_w, conv_b);           // launch 1
    k_stats_f<<<1, 256>>>(gamma, beta);                  // launch 2 (+pad)

    dim3 gf(64, 18);                                     // 16 fuse + 2 S-prep rows
    k_fuse_w<<<gf, 256>>>(x, conv_w, conv_b, trw, out);  // launch 3

    dim3 gg(KST, NTILE);
    k_gemm<<<gg, 256, SMEM_DYN>>>(trb);                  // launch 4 <- profiled

    dim3 g4(KST, BB);
    k_loss_part<<<g4, 256>>>(perm);                      // launch 5
    k_loss_fin<<<1, 32>>>(out + (size_t)BB * CC * LOUT); // launch 6
}